// round 1
// baseline (speedup 1.0000x reference)
#include <cuda_runtime.h>

#define SQ 2048
#define HID 1024
#define HEADS 16
#define HD 64
#define BSZ 2
#define BH (BSZ*HEADS)
#define ROWS_TOT (BSZ*SQ)

// scratch (allocation-free: device globals)
__device__ float g_q[BH*SQ*HD];
__device__ float g_k[BH*SQ*HD];
__device__ float g_v[BH*SQ*HD];
__device__ float g_vp[BH*SQ*HD];
__device__ float g_att[ROWS_TOT*HID];
__device__ float g_mod[HID];
__device__ float g_cs[SQ];
__device__ float g_sn[SQ];

// ---------------------------------------------------------------- prep
__global__ void prep_kernel(const float* __restrict__ phase,
                            const float* __restrict__ amp) {
    int i = blockIdx.x * 256 + threadIdx.x;
    if (i < HID) g_mod[i] = cosf(phase[i]) * amp[i];
    if (i < SQ) {
        float a = 6.283185307179586f * (float)i / (float)SQ;
        g_cs[i] = cosf(a);
        g_sn[i] = sinf(a);
    }
}

// ---------------------------------------------------------------- QKV GEMM
// C = X[4096,1024] @ W[1024,1024]; epilogue scatters to [B,H,S,D] with mod
// (and 1/sqrt(D) folded into q). grid = (8, 32, 3), block = 256.
__global__ __launch_bounds__(256) void qkv_gemm(const float* __restrict__ X,
                                                const float* __restrict__ Wq,
                                                const float* __restrict__ Wk,
                                                const float* __restrict__ Wv) {
    __shared__ __align__(16) float As[8][128];
    __shared__ __align__(16) float Bs[8][128];

    int mode = blockIdx.z;
    const float* W = (mode == 0) ? Wq : (mode == 1) ? Wk : Wv;
    float* dst = (mode == 0) ? g_q : (mode == 1) ? g_k : g_v;

    int bn = blockIdx.x, bm = blockIdx.y;
    int tid = threadIdx.x;
    int tx = tid & 15, ty = tid >> 4;
    int arow = tid >> 1, acol = (tid & 1) * 4;
    int brow = tid >> 5, bcol = (tid & 31) * 4;

    const float* Aptr = X + (size_t)(bm * 128 + arow) * HID + acol;
    const float* Bptr = W + (size_t)brow * HID + bn * 128 + bcol;

    float acc[8][8];
#pragma unroll
    for (int i = 0; i < 8; i++)
#pragma unroll
        for (int j = 0; j < 8; j++) acc[i][j] = 0.f;

    for (int k0 = 0; k0 < HID; k0 += 8) {
        float4 a4 = *(const float4*)(Aptr + k0);
        float4 b4 = *(const float4*)(Bptr + (size_t)k0 * HID);
        __syncthreads();
        As[acol + 0][arow] = a4.x;
        As[acol + 1][arow] = a4.y;
        As[acol + 2][arow] = a4.z;
        As[acol + 3][arow] = a4.w;
        *(float4*)&Bs[brow][bcol] = b4;
        __syncthreads();
#pragma unroll
        for (int kk = 0; kk < 8; kk++) {
            float av[8], bv[8];
            float4 t0 = *(const float4*)&As[kk][ty * 8];
            float4 t1 = *(const float4*)&As[kk][ty * 8 + 4];
            av[0]=t0.x; av[1]=t0.y; av[2]=t0.z; av[3]=t0.w;
            av[4]=t1.x; av[5]=t1.y; av[6]=t1.z; av[7]=t1.w;
            float4 u0 = *(const float4*)&Bs[kk][tx * 8];
            float4 u1 = *(const float4*)&Bs[kk][tx * 8 + 4];
            bv[0]=u0.x; bv[1]=u0.y; bv[2]=u0.z; bv[3]=u0.w;
            bv[4]=u1.x; bv[5]=u1.y; bv[6]=u1.z; bv[7]=u1.w;
#pragma unroll
            for (int i = 0; i < 8; i++)
#pragma unroll
                for (int j = 0; j < 8; j++) acc[i][j] += av[i] * bv[j];
        }
    }

    // epilogue: scale by mod (q also by 1/8), scatter to [B,H,S,D]
    float sc = (mode == 0) ? 0.125f : 1.0f;
    int colbase = bn * 128 + tx * 8;
    float mv[8];
#pragma unroll
    for (int j = 0; j < 8; j++) mv[j] = g_mod[colbase + j] * sc;
    int row0 = bm * 128 + ty * 8;
#pragma unroll
    for (int i = 0; i < 8; i++) {
        int row = row0 + i;
        int b = row >> 11;
        int s = row & 2047;
#pragma unroll
        for (int jg = 0; jg < 8; jg += 4) {
            int col = colbase + jg;
            int h = col >> 6;
            int d = col & 63;
            float4 o;
            o.x = acc[i][jg + 0] * mv[jg + 0];
            o.y = acc[i][jg + 1] * mv[jg + 1];
            o.z = acc[i][jg + 2] * mv[jg + 2];
            o.w = acc[i][jg + 3] * mv[jg + 3];
            *(float4*)&dst[(((size_t)(b * HEADS + h) * SQ + s) * HD + d)] = o;
        }
    }
}

// ---------------------------------------------------------------- V roll
// v'[s] = (v[s] + v[(s+1)%S]) / sqrt(2)
__global__ void roll_kernel() {
    int idx = blockIdx.x * 256 + threadIdx.x;  // float4 index
    if (idx >= BH * SQ * (HD / 4)) return;
    int d4 = idx & 15;
    int rest = idx >> 4;
    int s = rest & (SQ - 1);
    int bh = rest >> 11;
    int s2 = (s + 1) & (SQ - 1);
    const float4* v = (const float4*)g_v;
    float4 a = v[(((size_t)bh * SQ + s) << 4) + d4];
    float4 b = v[(((size_t)bh * SQ + s2) << 4) + d4];
    float4 o;
    const float r = 0.7071067811865476f;
    o.x = (a.x + b.x) * r;
    o.y = (a.y + b.y) * r;
    o.z = (a.z + b.z) * r;
    o.w = (a.w + b.w) * r;
    ((float4*)g_vp)[idx] = o;
}

// ---------------------------------------------------------------- flash attention
// grid = (16 m-tiles, 16 heads, 2 batch), block = 256 (16x16, 8x8 score frag).
// smem: Qs[64][128]^T, Ks[64][128]^T, Vs[128][64], Ps[128][128], cos/sin vecs.
#define ATT_SMEM_FLOATS (64*128 + 64*128 + 128*64 + 128*128 + 4*128)

__global__ __launch_bounds__(256) void attn_kernel() {
    extern __shared__ float smem[];
    float* Qs = smem;                // [64][128] (transposed: [d][m])
    float* Ks = Qs + 64 * 128;       // [64][128] ([d][n])
    float* Vs = Ks + 64 * 128;       // [128][64] ([n][d])
    float* Ps = Vs + 128 * 64;       // [128][128] ([m][n])
    float* cm = Ps + 128 * 128;
    float* smr = cm + 128;
    float* cj = smr + 128;
    float* sj = cj + 128;

    int m0 = blockIdx.x * 128;
    int h = blockIdx.y, b = blockIdx.z;
    int bh = b * HEADS + h;
    const float* Qg = g_q + (size_t)bh * SQ * HD;
    const float* Kg = g_k + (size_t)bh * SQ * HD;
    const float* Vg = g_vp + (size_t)bh * SQ * HD;

    int tid = threadIdx.x;
    int tx = tid & 15, ty = tid >> 4;
    int lr = tid >> 4;           // load row group 0..15
    int ld4 = (tid & 15) * 4;    // load d offset

    // load Q tile transposed (once)
#pragma unroll
    for (int rr = 0; rr < 128; rr += 16) {
        int row = lr + rr;
        float4 v = *(const float4*)(Qg + (size_t)(m0 + row) * HD + ld4);
        Qs[(ld4 + 0) * 128 + row] = v.x;
        Qs[(ld4 + 1) * 128 + row] = v.y;
        Qs[(ld4 + 2) * 128 + row] = v.z;
        Qs[(ld4 + 3) * 128 + row] = v.w;
    }
    if (tid < 128) { cm[tid] = g_cs[m0 + tid]; smr[tid] = g_sn[m0 + tid]; }

    float mrow[8], lrow[8], o[8][4];
#pragma unroll
    for (int i = 0; i < 8; i++) {
        mrow[i] = -1e30f;
        lrow[i] = 0.f;
#pragma unroll
        for (int c = 0; c < 4; c++) o[i][c] = 0.f;
    }
    __syncthreads();

    float cmv[8], smv[8];
#pragma unroll
    for (int i = 0; i < 8; i++) { cmv[i] = cm[ty * 8 + i]; smv[i] = smr[ty * 8 + i]; }

    for (int n0 = 0; n0 < SQ; n0 += 128) {
        __syncthreads();  // previous PV done before overwriting Ks/Vs/cj/sj
#pragma unroll
        for (int rr = 0; rr < 128; rr += 16) {
            int row = lr + rr;
            float4 v = *(const float4*)(Kg + (size_t)(n0 + row) * HD + ld4);
            Ks[(ld4 + 0) * 128 + row] = v.x;
            Ks[(ld4 + 1) * 128 + row] = v.y;
            Ks[(ld4 + 2) * 128 + row] = v.z;
            Ks[(ld4 + 3) * 128 + row] = v.w;
            float4 w = *(const float4*)(Vg + (size_t)(n0 + row) * HD + ld4);
            *(float4*)&Vs[row * HD + ld4] = w;
        }
        if (tid < 128) { cj[tid] = g_cs[n0 + tid]; sj[tid] = g_sn[n0 + tid]; }
        __syncthreads();

        // S = Q K^T (q already carries mod * 1/8; k carries mod)
        float acc[8][8];
#pragma unroll
        for (int i = 0; i < 8; i++)
#pragma unroll
            for (int j = 0; j < 8; j++) acc[i][j] = 0.f;

#pragma unroll 8
        for (int kk = 0; kk < 64; kk++) {
            float av[8], bv[8];
            float4 a0 = *(const float4*)&Qs[kk * 128 + ty * 8];
            float4 a1 = *(const float4*)&Qs[kk * 128 + ty * 8 + 4];
            av[0]=a0.x; av[1]=a0.y; av[2]=a0.z; av[3]=a0.w;
            av[4]=a1.x; av[5]=a1.y; av[6]=a1.z; av[7]=a1.w;
            float4 b0 = *(const float4*)&Ks[kk * 128 + tx * 8];
            float4 b1 = *(const float4*)&Ks[kk * 128 + tx * 8 + 4];
            bv[0]=b0.x; bv[1]=b0.y; bv[2]=b0.z; bv[3]=b0.w;
            bv[4]=b1.x; bv[5]=b1.y; bv[6]=b1.z; bv[7]=b1.w;
#pragma unroll
            for (int i = 0; i < 8; i++)
#pragma unroll
                for (int j = 0; j < 8; j++) acc[i][j] += av[i] * bv[j];
        }

        float cjv[8], sjv[8];
#pragma unroll
        for (int j = 0; j < 8; j++) { cjv[j] = cj[tx * 8 + j]; sjv[j] = sj[tx * 8 + j]; }

        // interference modulation + online softmax
#pragma unroll
        for (int i = 0; i < 8; i++) {
            float p[8];
            float mx = -1e30f;
#pragma unroll
            for (int j = 0; j < 8; j++) {
                float sv = acc[i][j] * (cmv[i] * cjv[j] + smv[i] * sjv[j]);
                p[j] = sv;
                mx = fmaxf(mx, sv);
            }
#pragma unroll
            for (int off = 1; off < 16; off <<= 1)
                mx = fmaxf(mx, __shfl_xor_sync(0xffffffffu, mx, off));
            float mnew = fmaxf(mrow[i], mx);
            float alpha = __expf(mrow[i] - mnew);
            float sum = 0.f;
#pragma unroll
            for (int j = 0; j < 8; j++) {
                p[j] = __expf(p[j] - mnew);
                sum += p[j];
            }
#pragma unroll
            for (int off = 1; off < 16; off <<= 1)
                sum += __shfl_xor_sync(0xffffffffu, sum, off);
            lrow[i] = lrow[i] * alpha + sum;
            mrow[i] = mnew;
#pragma unroll
            for (int c = 0; c < 4; c++) o[i][c] *= alpha;
            float4 p0 = {p[0], p[1], p[2], p[3]};
            float4 p1 = {p[4], p[5], p[6], p[7]};
            *(float4*)&Ps[(ty * 8 + i) * 128 + tx * 8] = p0;
            *(float4*)&Ps[(ty * 8 + i) * 128 + tx * 8 + 4] = p1;
        }
        __syncthreads();

        // O += P @ V'
#pragma unroll 4
        for (int n = 0; n < 128; n++) {
            float4 bv = *(const float4*)&Vs[n * HD + tx * 4];
#pragma unroll
            for (int i = 0; i < 8; i++) {
                float a = Ps[(ty * 8 + i) * 128 + n];
                o[i][0] += a * bv.x;
                o[i][1] += a * bv.y;
                o[i][2] += a * bv.z;
                o[i][3] += a * bv.w;
            }
        }
    }

    // normalize + write to [B,S,H*D]
#pragma unroll
    for (int i = 0; i < 8; i++) {
        float inv = 1.0f / lrow[i];
        float4 w;
        w.x = o[i][0] * inv;
        w.y = o[i][1] * inv;
        w.z = o[i][2] * inv;
        w.w = o[i][3] * inv;
        int row = m0 + ty * 8 + i;
        *(float4*)&g_att[((size_t)(b * SQ + row)) * HID + h * HD + tx * 4] = w;
    }
}

// ---------------------------------------------------------------- output GEMM
// d_out = g_att[4096,1024] @ Wo[1024,1024]
__global__ __launch_bounds__(256) void out_gemm(const float* __restrict__ W,
                                                float* __restrict__ C) {
    __shared__ __align__(16) float As[8][128];
    __shared__ __align__(16) float Bs[8][128];

    int bn = blockIdx.x, bm = blockIdx.y;
    int tid = threadIdx.x;
    int tx = tid & 15, ty = tid >> 4;
    int arow = tid >> 1, acol = (tid & 1) * 4;
    int brow = tid >> 5, bcol = (tid & 31) * 4;

    const float* Aptr = g_att + (size_t)(bm * 128 + arow) * HID + acol;
    const float* Bptr = W + (size_t)brow * HID + bn * 128 + bcol;

    float acc[8][8];
#pragma unroll
    for (int i = 0; i < 8; i++)
#pragma unroll
        for (int j = 0; j < 8; j++) acc[i][j] = 0.f;

    for (int k0 = 0; k0 < HID; k0 += 8) {
        float4 a4 = *(const float4*)(Aptr + k0);
        float4 b4 = *(const float4*)(Bptr + (size_t)k0 * HID);
        __syncthreads();
        As[acol + 0][arow] = a4.x;
        As[acol + 1][arow] = a4.y;
        As[acol + 2][arow] = a4.z;
        As[acol + 3][arow] = a4.w;
        *(float4*)&Bs[brow][bcol] = b4;
        __syncthreads();
#pragma unroll
        for (int kk = 0; kk < 8; kk++) {
            float av[8], bv[8];
            float4 t0 = *(const float4*)&As[kk][ty * 8];
            float4 t1 = *(const float4*)&As[kk][ty * 8 + 4];
            av[0]=t0.x; av[1]=t0.y; av[2]=t0.z; av[3]=t0.w;
            av[4]=t1.x; av[5]=t1.y; av[6]=t1.z; av[7]=t1.w;
            float4 u0 = *(const float4*)&Bs[kk][tx * 8];
            float4 u1 = *(const float4*)&Bs[kk][tx * 8 + 4];
            bv[0]=u0.x; bv[1]=u0.y; bv[2]=u0.z; bv[3]=u0.w;
            bv[4]=u1.x; bv[5]=u1.y; bv[6]=u1.z; bv[7]=u1.w;
#pragma unroll
            for (int i = 0; i < 8; i++)
#pragma unroll
                for (int j = 0; j < 8; j++) acc[i][j] += av[i] * bv[j];
        }
    }

    int row0 = bm * 128 + ty * 8;
    int col0 = bn * 128 + tx * 8;
#pragma unroll
    for (int i = 0; i < 8; i++) {
#pragma unroll
        for (int jg = 0; jg < 8; jg += 4) {
            float4 o;
            o.x = acc[i][jg + 0];
            o.y = acc[i][jg + 1];
            o.z = acc[i][jg + 2];
            o.w = acc[i][jg + 3];
            *(float4*)&C[(size_t)(row0 + i) * HID + col0 + jg] = o;
        }
    }
}

// ---------------------------------------------------------------- launch
extern "C" void kernel_launch(void* const* d_in, const int* in_sizes, int n_in,
                              void* d_out, int out_size) {
    const float* x     = (const float*)d_in[0];
    const float* Wq    = (const float*)d_in[1];
    const float* Wk    = (const float*)d_in[2];
    const float* Wv    = (const float*)d_in[3];
    const float* Wo    = (const float*)d_in[4];
    const float* phase = (const float*)d_in[5];
    const float* amp   = (const float*)d_in[6];
    float* out = (float*)d_out;

    cudaFuncSetAttribute(attn_kernel, cudaFuncAttributeMaxDynamicSharedMemorySize,
                         ATT_SMEM_FLOATS * sizeof(float));

    prep_kernel<<<8, 256>>>(phase, amp);
    qkv_gemm<<<dim3(8, 32, 3), 256>>>(x, Wq, Wk, Wv);
    roll_kernel<<<(BH * SQ * (HD / 4)) / 256, 256>>>();
    attn_kernel<<<dim3(16, 16, 2), 256, ATT_SMEM_FLOATS * sizeof(float)>>>();
    out_gemm<<<dim3(8, 32), 256>>>(Wo, out);
}

// round 2
// speedup vs baseline: 2.5774x; 2.5774x over previous
#include <cuda_runtime.h>

#define SQ 2048
#define HID 1024
#define HEADS 16
#define HD 64
#define BSZ 2
#define BH (BSZ*HEADS)
#define ROWS_TOT (BSZ*SQ)

// scratch (allocation-free: device globals)
__device__ float g_q[BH*SQ*HD];
__device__ float g_k[BH*SQ*HD];
__device__ float g_v[BH*SQ*HD];
__device__ float g_vp[BH*SQ*HD];
__device__ float g_att[ROWS_TOT*HID];
__device__ float g_mod[HID];
__device__ float g_cs[SQ];
__device__ float g_sn[SQ];

__device__ __forceinline__ float tf32r(float x) {
    float y;
    asm("cvt.rna.tf32.f32 %0, %1;" : "=f"(y) : "f"(x));
    return y;
}
__device__ __forceinline__ unsigned fu(float x) { return __float_as_uint(x); }

#define MMA_TF32(d, a0, a1, a2, a3, b0, b1)                                        \
    asm volatile(                                                                   \
        "mma.sync.aligned.m16n8k8.row.col.f32.tf32.tf32.f32 "                       \
        "{%0,%1,%2,%3},{%4,%5,%6,%7},{%8,%9},{%0,%1,%2,%3};"                        \
        : "+f"(d[0]), "+f"(d[1]), "+f"(d[2]), "+f"(d[3])                            \
        : "r"(a0), "r"(a1), "r"(a2), "r"(a3), "r"(b0), "r"(b1))

// ---------------------------------------------------------------- prep
__global__ void prep_kernel(const float* __restrict__ phase,
                            const float* __restrict__ amp) {
    int i = blockIdx.x * 256 + threadIdx.x;
    if (i < HID) g_mod[i] = cosf(phase[i]) * amp[i];
    if (i < SQ) {
        float a = 6.283185307179586f * (float)i / (float)SQ;
        g_cs[i] = cosf(a);
        g_sn[i] = sinf(a);
    }
}

// ---------------------------------------------------------------- V roll
__global__ void roll_kernel() {
    int idx = blockIdx.x * 256 + threadIdx.x;  // float4 index
    if (idx >= BH * SQ * (HD / 4)) return;
    int d4 = idx & 15;
    int rest = idx >> 4;
    int s = rest & (SQ - 1);
    int bh = rest >> 11;
    int s2 = (s + 1) & (SQ - 1);
    const float4* v = (const float4*)g_v;
    float4 a = v[(((size_t)bh * SQ + s) << 4) + d4];
    float4 b = v[(((size_t)bh * SQ + s2) << 4) + d4];
    float4 o;
    const float r = 0.7071067811865476f;
    o.x = (a.x + b.x) * r;
    o.y = (a.y + b.y) * r;
    o.z = (a.z + b.z) * r;
    o.w = (a.w + b.w) * r;
    ((float4*)g_vp)[idx] = o;
}

// ---------------------------------------------------------------- TF32 GEMM (QKV)
// C = X[4096,1024] @ W[1024,1024], tile 128x128, kblock 32, 8 warps 2m x 4n.
#define LDA 36
#define LDB 136
#define GEMM_SMEM ((2*128*LDA + 2*32*LDB) * 4)

__global__ __launch_bounds__(256) void qkv_gemm(const float* __restrict__ X,
                                                const float* __restrict__ Wq,
                                                const float* __restrict__ Wk,
                                                const float* __restrict__ Wv) {
    extern __shared__ float smg[];
    float* As = smg;                  // [2][128*LDA]
    float* Bs = smg + 2 * 128 * LDA;  // [2][32*LDB]

    int mode = blockIdx.z;
    const float* W = (mode == 0) ? Wq : (mode == 1) ? Wk : Wv;
    float* dst = (mode == 0) ? g_q : (mode == 1) ? g_k : g_v;

    int bn = blockIdx.x, bm = blockIdx.y;
    int tid = threadIdx.x, lane = tid & 31, w = tid >> 5;
    int wm = w >> 2, wn = w & 3;
    int r = lane >> 2, c = lane & 3;

    int arow = tid >> 1, acol0 = (tid & 1) * 16;
    int brow = tid >> 3, bcol0 = (tid & 7) * 16;
    const float* Ag = X + (size_t)(bm * 128 + arow) * HID + acol0;
    const float* Bg = W + (size_t)brow * HID + bn * 128 + bcol0;

    float4 pa[4], pb[4];
#pragma unroll
    for (int q = 0; q < 4; q++) {
        pa[q] = *(const float4*)(Ag + q * 4);
        pb[q] = *(const float4*)(Bg + q * 4);
    }
#pragma unroll
    for (int q = 0; q < 4; q++) {
        float4 ta = {tf32r(pa[q].x), tf32r(pa[q].y), tf32r(pa[q].z), tf32r(pa[q].w)};
        *(float4*)&As[arow * LDA + acol0 + q * 4] = ta;
        float4 tb = {tf32r(pb[q].x), tf32r(pb[q].y), tf32r(pb[q].z), tf32r(pb[q].w)};
        *(float4*)&Bs[brow * LDB + bcol0 + q * 4] = tb;
    }
    __syncthreads();

    float acc[4][4][4];
#pragma unroll
    for (int i = 0; i < 4; i++)
#pragma unroll
        for (int j = 0; j < 4; j++)
#pragma unroll
            for (int e = 0; e < 4; e++) acc[i][j][e] = 0.f;

    for (int kb = 0; kb < 32; kb++) {
        const float* Ac = As + (kb & 1) * (128 * LDA);
        const float* Bc = Bs + (kb & 1) * (32 * LDB);
        if (kb < 31) {
            const float* Ag2 = Ag + (kb + 1) * 32;
            const float* Bg2 = Bg + (size_t)(kb + 1) * 32 * HID;
#pragma unroll
            for (int q = 0; q < 4; q++) {
                pa[q] = *(const float4*)(Ag2 + q * 4);
                pb[q] = *(const float4*)(Bg2 + q * 4);
            }
        }
#pragma unroll
        for (int kk = 0; kk < 4; kk++) {
            unsigned a[4][4], b[4][2];
#pragma unroll
            for (int i = 0; i < 4; i++) {
                const float* p = Ac + (wm * 64 + i * 16 + r) * LDA + kk * 8 + c;
                a[i][0] = fu(p[0]);
                a[i][1] = fu(p[8 * LDA]);
                a[i][2] = fu(p[4]);
                a[i][3] = fu(p[8 * LDA + 4]);
            }
#pragma unroll
            for (int j = 0; j < 4; j++) {
                const float* p = Bc + (kk * 8 + c) * LDB + wn * 32 + j * 8 + r;
                b[j][0] = fu(p[0]);
                b[j][1] = fu(p[4 * LDB]);
            }
#pragma unroll
            for (int i = 0; i < 4; i++)
#pragma unroll
                for (int j = 0; j < 4; j++)
                    MMA_TF32(acc[i][j], a[i][0], a[i][1], a[i][2], a[i][3],
                             b[j][0], b[j][1]);
        }
        if (kb < 31) {
            float* An = As + ((kb + 1) & 1) * (128 * LDA);
            float* Bn = Bs + ((kb + 1) & 1) * (32 * LDB);
#pragma unroll
            for (int q = 0; q < 4; q++) {
                float4 ta = {tf32r(pa[q].x), tf32r(pa[q].y), tf32r(pa[q].z), tf32r(pa[q].w)};
                *(float4*)&An[arow * LDA + acol0 + q * 4] = ta;
                float4 tb = {tf32r(pb[q].x), tf32r(pb[q].y), tf32r(pb[q].z), tf32r(pb[q].w)};
                *(float4*)&Bn[brow * LDB + bcol0 + q * 4] = tb;
            }
            __syncthreads();
        }
    }

    // epilogue: mod scale (q also 1/8), scatter to [B,H,S,D]
    float sc = (mode == 0) ? 0.125f : 1.0f;
#pragma unroll
    for (int i = 0; i < 4; i++) {
#pragma unroll
        for (int ro = 0; ro < 2; ro++) {
            int grow = bm * 128 + wm * 64 + i * 16 + r + ro * 8;
            int bb = grow >> 11;
            int ss = grow & 2047;
#pragma unroll
            for (int j = 0; j < 4; j++) {
                int col = bn * 128 + wn * 32 + j * 8 + 2 * c;
                int hh = col >> 6;
                int dd = col & 63;
                float m0v = g_mod[col] * sc;
                float m1v = g_mod[col + 1] * sc;
                float2 v;
                v.x = acc[i][j][ro * 2 + 0] * m0v;
                v.y = acc[i][j][ro * 2 + 1] * m1v;
                *(float2*)&dst[(((size_t)(bb * HEADS + hh) * SQ + ss) * HD + dd)] = v;
            }
        }
    }
}

// ---------------------------------------------------------------- TF32 GEMM (out)
__global__ __launch_bounds__(256) void out_gemm(const float* __restrict__ W,
                                                float* __restrict__ C) {
    extern __shared__ float smg[];
    float* As = smg;
    float* Bs = smg + 2 * 128 * LDA;

    int bn = blockIdx.x, bm = blockIdx.y;
    int tid = threadIdx.x, lane = tid & 31, w = tid >> 5;
    int wm = w >> 2, wn = w & 3;
    int r = lane >> 2, c = lane & 3;

    int arow = tid >> 1, acol0 = (tid & 1) * 16;
    int brow = tid >> 3, bcol0 = (tid & 7) * 16;
    const float* Ag = g_att + (size_t)(bm * 128 + arow) * HID + acol0;
    const float* Bg = W + (size_t)brow * HID + bn * 128 + bcol0;

    float4 pa[4], pb[4];
#pragma unroll
    for (int q = 0; q < 4; q++) {
        pa[q] = *(const float4*)(Ag + q * 4);
        pb[q] = *(const float4*)(Bg + q * 4);
    }
#pragma unroll
    for (int q = 0; q < 4; q++) {
        float4 ta = {tf32r(pa[q].x), tf32r(pa[q].y), tf32r(pa[q].z), tf32r(pa[q].w)};
        *(float4*)&As[arow * LDA + acol0 + q * 4] = ta;
        float4 tb = {tf32r(pb[q].x), tf32r(pb[q].y), tf32r(pb[q].z), tf32r(pb[q].w)};
        *(float4*)&Bs[brow * LDB + bcol0 + q * 4] = tb;
    }
    __syncthreads();

    float acc[4][4][4];
#pragma unroll
    for (int i = 0; i < 4; i++)
#pragma unroll
        for (int j = 0; j < 4; j++)
#pragma unroll
            for (int e = 0; e < 4; e++) acc[i][j][e] = 0.f;

    for (int kb = 0; kb < 32; kb++) {
        const float* Ac = As + (kb & 1) * (128 * LDA);
        const float* Bc = Bs + (kb & 1) * (32 * LDB);
        if (kb < 31) {
            const float* Ag2 = Ag + (kb + 1) * 32;
            const float* Bg2 = Bg + (size_t)(kb + 1) * 32 * HID;
#pragma unroll
            for (int q = 0; q < 4; q++) {
                pa[q] = *(const float4*)(Ag2 + q * 4);
                pb[q] = *(const float4*)(Bg2 + q * 4);
            }
        }
#pragma unroll
        for (int kk = 0; kk < 4; kk++) {
            unsigned a[4][4], b[4][2];
#pragma unroll
            for (int i = 0; i < 4; i++) {
                const float* p = Ac + (wm * 64 + i * 16 + r) * LDA + kk * 8 + c;
                a[i][0] = fu(p[0]);
                a[i][1] = fu(p[8 * LDA]);
                a[i][2] = fu(p[4]);
                a[i][3] = fu(p[8 * LDA + 4]);
            }
#pragma unroll
            for (int j = 0; j < 4; j++) {
                const float* p = Bc + (kk * 8 + c) * LDB + wn * 32 + j * 8 + r;
                b[j][0] = fu(p[0]);
                b[j][1] = fu(p[4 * LDB]);
            }
#pragma unroll
            for (int i = 0; i < 4; i++)
#pragma unroll
                for (int j = 0; j < 4; j++)
                    MMA_TF32(acc[i][j], a[i][0], a[i][1], a[i][2], a[i][3],
                             b[j][0], b[j][1]);
        }
        if (kb < 31) {
            float* An = As + ((kb + 1) & 1) * (128 * LDA);
            float* Bn = Bs + ((kb + 1) & 1) * (32 * LDB);
#pragma unroll
            for (int q = 0; q < 4; q++) {
                float4 ta = {tf32r(pa[q].x), tf32r(pa[q].y), tf32r(pa[q].z), tf32r(pa[q].w)};
                *(float4*)&An[arow * LDA + acol0 + q * 4] = ta;
                float4 tb = {tf32r(pb[q].x), tf32r(pb[q].y), tf32r(pb[q].z), tf32r(pb[q].w)};
                *(float4*)&Bn[brow * LDB + bcol0 + q * 4] = tb;
            }
            __syncthreads();
        }
    }

#pragma unroll
    for (int i = 0; i < 4; i++) {
#pragma unroll
        for (int ro = 0; ro < 2; ro++) {
            int grow = bm * 128 + wm * 64 + i * 16 + r + ro * 8;
#pragma unroll
            for (int j = 0; j < 4; j++) {
                int col = bn * 128 + wn * 32 + j * 8 + 2 * c;
                float2 v;
                v.x = acc[i][j][ro * 2 + 0];
                v.y = acc[i][j][ro * 2 + 1];
                *(float2*)&C[(size_t)grow * HID + col] = v;
            }
        }
    }
}

// ---------------------------------------------------------------- flash attention (TF32 mma)
// grid (16,16,2), 256 thr = 8 warps; warp w owns S rows [w*16, w*16+16).
#define LDQ 68
#define LDK 68
#define LDV 72
#define LDP 132
#define ATT_SMEM ((128*LDQ + 128*LDK + 128*LDV + 128*LDP + 256) * 4)

__global__ __launch_bounds__(256) void attn_kernel() {
    extern __shared__ float sma[];
    float* Qs = sma;
    float* Ks = Qs + 128 * LDQ;
    float* Vs = Ks + 128 * LDK;
    float* Ps = Vs + 128 * LDV;
    float* cjs = Ps + 128 * LDP;
    float* sjs = cjs + 128;

    int m0 = blockIdx.x * 128;
    int h = blockIdx.y, b = blockIdx.z;
    int bh = b * HEADS + h;
    const float* Qg = g_q + (size_t)bh * SQ * HD;
    const float* Kg = g_k + (size_t)bh * SQ * HD;
    const float* Vg = g_vp + (size_t)bh * SQ * HD;

    int tid = threadIdx.x, lane = tid & 31, w = tid >> 5;
    int r = lane >> 2, c = lane & 3;
    int lr = tid >> 4, lc = (tid & 15) * 4;

    // load Q tile (tf32-converted)
#pragma unroll
    for (int rr = 0; rr < 8; rr++) {
        int row = rr * 16 + lr;
        float4 v = *(const float4*)(Qg + (size_t)(m0 + row) * HD + lc);
        float4 t = {tf32r(v.x), tf32r(v.y), tf32r(v.z), tf32r(v.w)};
        *(float4*)&Qs[row * LDQ + lc] = t;
    }

    // per-thread row trig + online-softmax state
    float cmv[2], smv[2], ms[2], ls[2];
#pragma unroll
    for (int ro = 0; ro < 2; ro++) {
        int row = m0 + w * 16 + r + ro * 8;
        cmv[ro] = g_cs[row];
        smv[ro] = g_sn[row];
        ms[ro] = -1e30f;
        ls[ro] = 0.f;
    }
    float o[8][4];
#pragma unroll
    for (int j = 0; j < 8; j++)
#pragma unroll
        for (int e = 0; e < 4; e++) o[j][e] = 0.f;

    for (int n0 = 0; n0 < SQ; n0 += 128) {
        __syncthreads();
        // load K, V tiles + trig vectors
#pragma unroll
        for (int rr = 0; rr < 8; rr++) {
            int row = rr * 16 + lr;
            float4 v = *(const float4*)(Kg + (size_t)(n0 + row) * HD + lc);
            float4 t = {tf32r(v.x), tf32r(v.y), tf32r(v.z), tf32r(v.w)};
            *(float4*)&Ks[row * LDK + lc] = t;
            float4 u = *(const float4*)(Vg + (size_t)(n0 + row) * HD + lc);
            float4 s = {tf32r(u.x), tf32r(u.y), tf32r(u.z), tf32r(u.w)};
            *(float4*)&Vs[row * LDV + lc] = s;
        }
        if (tid < 128) {
            cjs[tid] = g_cs[n0 + tid];
            sjs[tid] = g_sn[n0 + tid];
        }
        __syncthreads();

        // S = Q K^T : warp tile m16 x n128
        float s[16][4];
#pragma unroll
        for (int j = 0; j < 16; j++)
#pragma unroll
            for (int e = 0; e < 4; e++) s[j][e] = 0.f;

#pragma unroll
        for (int kk = 0; kk < 8; kk++) {
            unsigned a0, a1, a2, a3;
            const float* qp = &Qs[(w * 16 + r) * LDQ + kk * 8 + c];
            a0 = fu(qp[0]);
            a1 = fu(qp[8 * LDQ]);
            a2 = fu(qp[4]);
            a3 = fu(qp[8 * LDQ + 4]);
#pragma unroll
            for (int j = 0; j < 16; j++) {
                const float* kp = &Ks[(j * 8 + r) * LDK + kk * 8 + c];
                unsigned b0 = fu(kp[0]);
                unsigned b1 = fu(kp[4]);
                MMA_TF32(s[j], a0, a1, a2, a3, b0, b1);
            }
        }

        // interference modulation
#pragma unroll
        for (int j = 0; j < 16; j++) {
            int col = j * 8 + 2 * c;
            float cj0 = cjs[col], cj1 = cjs[col + 1];
            float sj0 = sjs[col], sj1 = sjs[col + 1];
            s[j][0] *= (cmv[0] * cj0 + smv[0] * sj0);
            s[j][1] *= (cmv[0] * cj1 + smv[0] * sj1);
            s[j][2] *= (cmv[1] * cj0 + smv[1] * sj0);
            s[j][3] *= (cmv[1] * cj1 + smv[1] * sj1);
        }

        // online softmax per row group
#pragma unroll
        for (int ro = 0; ro < 2; ro++) {
            float mx = -1e30f;
#pragma unroll
            for (int j = 0; j < 16; j++)
                mx = fmaxf(mx, fmaxf(s[j][ro * 2], s[j][ro * 2 + 1]));
            mx = fmaxf(mx, __shfl_xor_sync(0xffffffffu, mx, 1));
            mx = fmaxf(mx, __shfl_xor_sync(0xffffffffu, mx, 2));
            float mn = fmaxf(ms[ro], mx);
            float al = __expf(ms[ro] - mn);
            float sum = 0.f;
#pragma unroll
            for (int j = 0; j < 16; j++) {
                float p0 = __expf(s[j][ro * 2] - mn);
                float p1 = __expf(s[j][ro * 2 + 1] - mn);
                s[j][ro * 2] = p0;
                s[j][ro * 2 + 1] = p1;
                sum += p0 + p1;
            }
            sum += __shfl_xor_sync(0xffffffffu, sum, 1);
            sum += __shfl_xor_sync(0xffffffffu, sum, 2);
            ls[ro] = ls[ro] * al + sum;
            ms[ro] = mn;
#pragma unroll
            for (int j2 = 0; j2 < 8; j2++) {
                o[j2][ro * 2] *= al;
                o[j2][ro * 2 + 1] *= al;
            }
        }

        // write P (tf32) for PV mma
        {
            int row0 = w * 16 + r;
#pragma unroll
            for (int j = 0; j < 16; j++) {
                int col = j * 8 + 2 * c;
                Ps[row0 * LDP + col] = tf32r(s[j][0]);
                Ps[row0 * LDP + col + 1] = tf32r(s[j][1]);
                Ps[(row0 + 8) * LDP + col] = tf32r(s[j][2]);
                Ps[(row0 + 8) * LDP + col + 1] = tf32r(s[j][3]);
            }
        }
        __syncthreads();

        // O += P @ V' : warp tile m16 x n64, k=128
#pragma unroll
        for (int kk2 = 0; kk2 < 16; kk2++) {
            unsigned a0, a1, a2, a3;
            const float* pp = &Ps[(w * 16 + r) * LDP + kk2 * 8 + c];
            a0 = fu(pp[0]);
            a1 = fu(pp[8 * LDP]);
            a2 = fu(pp[4]);
            a3 = fu(pp[8 * LDP + 4]);
#pragma unroll
            for (int j2 = 0; j2 < 8; j2++) {
                const float* vp = &Vs[(kk2 * 8 + c) * LDV + j2 * 8 + r];
                unsigned b0 = fu(vp[0]);
                unsigned b1 = fu(vp[4 * LDV]);
                MMA_TF32(o[j2], a0, a1, a2, a3, b0, b1);
            }
        }
    }

    // epilogue: normalize + write [B,S,H*D]
#pragma unroll
    for (int ro = 0; ro < 2; ro++) {
        float inv = 1.0f / ls[ro];
        int row = m0 + w * 16 + r + ro * 8;
#pragma unroll
        for (int j2 = 0; j2 < 8; j2++) {
            int col = j2 * 8 + 2 * c;
            float2 v;
            v.x = o[j2][ro * 2] * inv;
            v.y = o[j2][ro * 2 + 1] * inv;
            *(float2*)&g_att[((size_t)(b * SQ + row)) * HID + h * HD + col] = v;
        }
    }
}

// ---------------------------------------------------------------- launch
extern "C" void kernel_launch(void* const* d_in, const int* in_sizes, int n_in,
                              void* d_out, int out_size) {
    const float* x     = (const float*)d_in[0];
    const float* Wq    = (const float*)d_in[1];
    const float* Wk    = (const float*)d_in[2];
    const float* Wv    = (const float*)d_in[3];
    const float* Wo    = (const float*)d_in[4];
    const float* phase = (const float*)d_in[5];
    const float* amp   = (const float*)d_in[6];
    float* out = (float*)d_out;

    cudaFuncSetAttribute(qkv_gemm, cudaFuncAttributeMaxDynamicSharedMemorySize, GEMM_SMEM);
    cudaFuncSetAttribute(out_gemm, cudaFuncAttributeMaxDynamicSharedMemorySize, GEMM_SMEM);
    cudaFuncSetAttribute(attn_kernel, cudaFuncAttributeMaxDynamicSharedMemorySize, ATT_SMEM);

    prep_kernel<<<8, 256>>>(phase, amp);
    qkv_gemm<<<dim3(8, 32, 3), 256, GEMM_SMEM>>>(x, Wq, Wk, Wv);
    roll_kernel<<<(BH * SQ * (HD / 4)) / 256, 256>>>();
    attn_kernel<<<dim3(16, 16, 2), 256, ATT_SMEM>>>();
    out_gemm<<<dim3(8, 32), 256, GEMM_SMEM>>>(Wo, out);
}